// round 15
// baseline (speedup 1.0000x reference)
#include <cuda_runtime.h>
#include <cuda_fp16.h>
#include <cstdint>

#define M_DIM 8192
#define N_DIM 1024
#define IN_DIM 1024
#define KV 4096              // virtual K = IN*4

#define BM 128
#define BN 128
#define KC 32                // fp16 elems per K-chunk
#define NCHUNK (KV / KC)     // 128
#define THREADS 256
#define STAGES 4

#define ROWB 80                       // padded row stride: 64B data + 16B pad
#define TILEB (128 * ROWB)            // 10240 B per [128 x 32] fp16 tile
#define STAGE_BYTES (2 * TILEB)       // Ah, Bh = 20480 B
#define SMEM_ALLOC (STAGES * STAGE_BYTES)   // 81920 B -> 2 CTAs/SM

// ---------------------------------------------------------------------------
// Scratch (__device__ globals; allocation-free rule)
// ---------------------------------------------------------------------------
__device__ __align__(1024) __half g_Fh[(size_t)M_DIM * KV];  // 64 MB  A (fp16)
__device__ __align__(1024) __half g_Bh[(size_t)N_DIM * KV];  //  8 MB  B (fp16)
__device__ __align__(16)   float  g_biasp[N_DIM];

// ---------------------------------------------------------------------------
// PTX helpers (baseline ISA only: cp.async / ldmatrix / mma.sync)
// ---------------------------------------------------------------------------
__device__ __forceinline__ void cpa16(uint32_t s, const void* g) {
    asm volatile("cp.async.cg.shared.global [%0], [%1], 16;" :: "r"(s), "l"(g));
}
#define CP_COMMIT() asm volatile("cp.async.commit_group;" ::: "memory")

__device__ __forceinline__ void ldm4(uint32_t* r, uint32_t a) {
    asm volatile("ldmatrix.sync.aligned.m8n8.x4.shared.b16 {%0,%1,%2,%3}, [%4];"
                 : "=r"(r[0]), "=r"(r[1]), "=r"(r[2]), "=r"(r[3]) : "r"(a));
}

__device__ __forceinline__ void mma16816(float* d, const uint32_t* a,
                                         const uint32_t* b) {
    asm volatile(
        "mma.sync.aligned.m16n8k16.row.col.f32.f16.f16.f32 "
        "{%0,%1,%2,%3}, {%4,%5,%6,%7}, {%8,%9}, {%0,%1,%2,%3};"
        : "+f"(d[0]), "+f"(d[1]), "+f"(d[2]), "+f"(d[3])
        : "r"(a[0]), "r"(a[1]), "r"(a[2]), "r"(a[3]), "r"(b[0]), "r"(b[1]));
}

// ---------------------------------------------------------------------------
// Feature map -> fp16: F[b][i*4+{0..3}] = x, x^2, x^3, silu(x)
// ---------------------------------------------------------------------------
__global__ void feat_kernel(const float* __restrict__ x) {
    int idx = blockIdx.x * blockDim.x + threadIdx.x;
    if (idx >= M_DIM * IN_DIM) return;
    float v  = x[idx];
    float v2 = v * v;
    float v3 = v2 * v;
    float s  = v / (1.0f + expf(-v));
    union { __half h[4]; uint2 u; } H;
    H.h[0] = __float2half(v);
    H.h[1] = __float2half(v2);
    H.h[2] = __float2half(v3);
    H.h[3] = __float2half(s);
    reinterpret_cast<uint2*>(g_Fh)[idx] = H.u;
}

// ---------------------------------------------------------------------------
// Weight pack -> fp16, K-major: B[o][i*4+{0..3}] = {C1, C2, C3, W}
// ---------------------------------------------------------------------------
__global__ void pack_kernel(const float* __restrict__ tc,
                            const float* __restrict__ bw) {
    int idx = blockIdx.x * blockDim.x + threadIdx.x;
    if (idx >= N_DIM * IN_DIM) return;
    int i = idx & (IN_DIM - 1);
    int o = idx >> 10;
    float4 c = reinterpret_cast<const float4*>(tc)[(size_t)o * IN_DIM + i];
    float  w = bw[(size_t)o * IN_DIM + i];
    union { __half h[4]; uint2 u; } H;
    H.h[0] = __float2half(c.y);
    H.h[1] = __float2half(c.z);
    H.h[2] = __float2half(c.w);
    H.h[3] = __float2half(w);
    reinterpret_cast<uint2*>(g_Bh)[(size_t)o * IN_DIM + i] = H.u;
}

// ---------------------------------------------------------------------------
// bias'[o] = bias[o] + sum_i C[o,i,0]
// ---------------------------------------------------------------------------
__global__ void bias_kernel(const float* __restrict__ tc,
                            const float* __restrict__ bias) {
    int o = blockIdx.x;
    float s = 0.f;
    for (int i = threadIdx.x; i < IN_DIM; i += 256)
        s += tc[(size_t)o * (IN_DIM * 4) + (size_t)i * 4];
    #pragma unroll
    for (int off = 16; off; off >>= 1)
        s += __shfl_down_sync(0xffffffffu, s, off);
    __shared__ float red[8];
    if ((threadIdx.x & 31) == 0) red[threadIdx.x >> 5] = s;
    __syncthreads();
    if (threadIdx.x < 8) {
        s = red[threadIdx.x];
        #pragma unroll
        for (int off = 4; off; off >>= 1)
            s += __shfl_down_sync(0xffu, s, off);
        if (threadIdx.x == 0) g_biasp[o] = s + bias[o];
    }
}

// ---------------------------------------------------------------------------
// Load one pipeline stage: Ah [128x32] + Bh [128x32] fp16, padded 80B rows.
// 4 x cp.async(16B) per thread.
// ---------------------------------------------------------------------------
__device__ __forceinline__ void load_stage(uint32_t stg, int k0, int bm, int bn,
                                           int tid) {
    #pragma unroll
    for (int r = 0; r < 2; r++) {
        int s   = tid + r * THREADS;       // 0..511
        int row = s >> 2;                  // 0..127
        int c   = s & 3;                   // 16B seg within 64B row
        uint32_t so = (uint32_t)(row * ROWB + c * 16);
        size_t ga = (size_t)(bm + row) * KV + k0 + c * 8;
        size_t gb = (size_t)(bn + row) * KV + k0 + c * 8;
        cpa16(stg + 0 * TILEB + so, g_Fh + ga);
        cpa16(stg + 1 * TILEB + so, g_Bh + gb);
    }
}

// ---------------------------------------------------------------------------
// GEMM via mma.sync fp16, single pass: out = Ah@Bh^T + bias
// 8 warps, warp tile 64x32 (4x4 grid of m16n8k16). 2 CTAs/SM, 4-stage pipe.
// ---------------------------------------------------------------------------
__global__ void __launch_bounds__(THREADS, 2) gemm_kernel(float* __restrict__ out) {
    extern __shared__ __align__(128) char smem_raw[];
    const int tid    = threadIdx.x;
    const int wid    = tid >> 5;
    const int lane   = tid & 31;
    const int warp_m = wid >> 2;           // 0..1  -> 64 rows
    const int warp_n = wid & 3;            // 0..3  -> 32 cols
    const int bm     = blockIdx.y * BM;
    const int bn     = blockIdx.x * BN;

    const uint32_t sb = (uint32_t)__cvta_generic_to_shared(smem_raw);

    // per-thread invariant ldmatrix offsets
    const uint32_t a_off = (uint32_t)((warp_m * 64 + (lane & 15)) * ROWB +
                                      (lane >> 4) * 16);
    const int bquad = lane >> 3;           // 0..3
    const uint32_t b_off = (uint32_t)((warp_n * 32 + ((bquad >> 1) * 8) +
                                       (lane & 7)) * ROWB + (bquad & 1) * 16);

    float acc[4][4][4];
    #pragma unroll
    for (int mi = 0; mi < 4; mi++)
        #pragma unroll
        for (int ni = 0; ni < 4; ni++)
            #pragma unroll
            for (int q = 0; q < 4; q++) acc[mi][ni][q] = 0.f;

    // Prologue: stages 0..2
    load_stage(sb + 0 * STAGE_BYTES, 0 * KC, bm, bn, tid);
    CP_COMMIT();
    load_stage(sb + 1 * STAGE_BYTES, 1 * KC, bm, bn, tid);
    CP_COMMIT();
    load_stage(sb + 2 * STAGE_BYTES, 2 * KC, bm, bn, tid);
    CP_COMMIT();

    #pragma unroll 1
    for (int i = 0; i < NCHUNK; i++) {
        if      (i <= NCHUNK - 3) asm volatile("cp.async.wait_group 2;" ::: "memory");
        else if (i == NCHUNK - 2) asm volatile("cp.async.wait_group 1;" ::: "memory");
        else                      asm volatile("cp.async.wait_group 0;" ::: "memory");
        __syncthreads();

        const uint32_t stg = sb + (uint32_t)(i % STAGES) * STAGE_BYTES;

        if (i + 3 < NCHUNK) {
            load_stage(sb + (uint32_t)((i + 3) % STAGES) * STAGE_BYTES,
                       (i + 3) * KC, bm, bn, tid);
            CP_COMMIT();
        }

        #pragma unroll
        for (int ks = 0; ks < 2; ks++) {
            uint32_t ah[4][4], bh[2][4];
            const uint32_t kso = (uint32_t)(ks * 32);
            #pragma unroll
            for (int mi = 0; mi < 4; mi++) {
                uint32_t ao = a_off + (uint32_t)(mi * 16 * ROWB) + kso;
                ldm4(ah[mi], stg + 0 * TILEB + ao);
            }
            #pragma unroll
            for (int p = 0; p < 2; p++) {
                uint32_t bo = b_off + (uint32_t)(p * 16 * ROWB) + kso;
                ldm4(bh[p], stg + 1 * TILEB + bo);
            }
            #pragma unroll
            for (int mi = 0; mi < 4; mi++)
                #pragma unroll
                for (int ni = 0; ni < 4; ni++)
                    mma16816(acc[mi][ni], ah[mi], &bh[ni >> 1][(ni & 1) * 2]);
        }
    }

    // Epilogue: bias + store (float2 per fragment pair)
    #pragma unroll
    for (int mi = 0; mi < 4; mi++) {
        const int r0 = bm + warp_m * 64 + mi * 16 + (lane >> 2);
        #pragma unroll
        for (int ni = 0; ni < 4; ni++) {
            const int c = bn + warp_n * 32 + ni * 8 + (lane & 3) * 2;
            const float b0 = g_biasp[c];
            const float b1 = g_biasp[c + 1];
            float2 v0 = make_float2(acc[mi][ni][0] + b0, acc[mi][ni][1] + b1);
            float2 v1 = make_float2(acc[mi][ni][2] + b0, acc[mi][ni][3] + b1);
            *reinterpret_cast<float2*>(out + (size_t)r0 * N_DIM + c)       = v0;
            *reinterpret_cast<float2*>(out + (size_t)(r0 + 8) * N_DIM + c) = v1;
        }
    }
}

// ---------------------------------------------------------------------------
extern "C" void kernel_launch(void* const* d_in, const int* in_sizes, int n_in,
                              void* d_out, int out_size) {
    const float* x = nullptr;
    const float* bw = nullptr;
    const float* tc = nullptr;
    const float* bias = nullptr;
    for (int i = 0; i < n_in; i++) {
        long sz = in_sizes[i];
        if      (sz == 8388608L) x    = (const float*)d_in[i];
        else if (sz == 1048576L) bw   = (const float*)d_in[i];
        else if (sz == 4194304L) tc   = (const float*)d_in[i];
        else if (sz == 1024L)    bias = (const float*)d_in[i];
    }
    float* out = (float*)d_out;

    cudaFuncSetAttribute(gemm_kernel,
                         cudaFuncAttributeMaxDynamicSharedMemorySize, SMEM_ALLOC);

    feat_kernel<<<(M_DIM * IN_DIM) / 256, 256>>>(x);
    pack_kernel<<<(N_DIM * IN_DIM) / 256, 256>>>(tc, bw);
    bias_kernel<<<N_DIM, 256>>>(tc, bias);

    dim3 grid(N_DIM / BN, M_DIM / BM);   // (8, 64) = 512 CTAs
    gemm_kernel<<<grid, THREADS, SMEM_ALLOC>>>(out);
}

// round 16
// speedup vs baseline: 1.0020x; 1.0020x over previous
#include <cuda_runtime.h>
#include <cuda_fp16.h>
#include <cstdint>

#define M_DIM 8192
#define N_DIM 1024
#define IN_DIM 1024
#define KV 4096              // virtual K = IN*4

#define BM 128
#define BN 128
#define KC 32                // fp16 elems per K-chunk
#define NCHUNK (KV / KC)     // 128
#define THREADS 256
#define STAGES 4

#define ROWB 80                       // padded row stride: 64B data + 16B pad
#define TILEB (128 * ROWB)            // 10240 B per [128 x 32] fp16 tile
#define STAGE_BYTES (2 * TILEB)       // Ah, Bh = 20480 B
#define SMEM_ALLOC (STAGES * STAGE_BYTES)   // 81920 B -> 2 CTAs/SM

// ---------------------------------------------------------------------------
// Scratch (__device__ globals; allocation-free rule)
// ---------------------------------------------------------------------------
__device__ __align__(1024) __half g_Fh[(size_t)M_DIM * KV];  // 64 MB  A (fp16)
__device__ __align__(1024) __half g_Bh[(size_t)N_DIM * KV];  //  8 MB  B (fp16)
__device__ __align__(16)   float  g_biasp[N_DIM];

// ---------------------------------------------------------------------------
// PTX helpers (baseline ISA only: cp.async / ldmatrix / mma.sync)
// ---------------------------------------------------------------------------
__device__ __forceinline__ void cpa16(uint32_t s, const void* g) {
    asm volatile("cp.async.cg.shared.global [%0], [%1], 16;" :: "r"(s), "l"(g));
}
#define CP_COMMIT() asm volatile("cp.async.commit_group;" ::: "memory")

__device__ __forceinline__ void ldm4(uint32_t* r, uint32_t a) {
    asm volatile("ldmatrix.sync.aligned.m8n8.x4.shared.b16 {%0,%1,%2,%3}, [%4];"
                 : "=r"(r[0]), "=r"(r[1]), "=r"(r[2]), "=r"(r[3]) : "r"(a));
}

__device__ __forceinline__ void mma16816(float* d, const uint32_t* a,
                                         const uint32_t* b) {
    asm volatile(
        "mma.sync.aligned.m16n8k16.row.col.f32.f16.f16.f32 "
        "{%0,%1,%2,%3}, {%4,%5,%6,%7}, {%8,%9}, {%0,%1,%2,%3};"
        : "+f"(d[0]), "+f"(d[1]), "+f"(d[2]), "+f"(d[3])
        : "r"(a[0]), "r"(a[1]), "r"(a[2]), "r"(a[3]), "r"(b[0]), "r"(b[1]));
}

// ---------------------------------------------------------------------------
// Feature map -> fp16: F[b][i*4+{0..3}] = x, x^2, x^3, silu(x)
// ---------------------------------------------------------------------------
__global__ void feat_kernel(const float* __restrict__ x) {
    int idx = blockIdx.x * blockDim.x + threadIdx.x;
    if (idx >= M_DIM * IN_DIM) return;
    float v  = x[idx];
    float v2 = v * v;
    float v3 = v2 * v;
    float s  = v / (1.0f + expf(-v));
    union { __half h[4]; uint2 u; } H;
    H.h[0] = __float2half(v);
    H.h[1] = __float2half(v2);
    H.h[2] = __float2half(v3);
    H.h[3] = __float2half(s);
    reinterpret_cast<uint2*>(g_Fh)[idx] = H.u;
}

// ---------------------------------------------------------------------------
// Weight pack -> fp16, K-major: B[o][i*4+{0..3}] = {C1, C2, C3, W}
// ---------------------------------------------------------------------------
__global__ void pack_kernel(const float* __restrict__ tc,
                            const float* __restrict__ bw) {
    int idx = blockIdx.x * blockDim.x + threadIdx.x;
    if (idx >= N_DIM * IN_DIM) return;
    int i = idx & (IN_DIM - 1);
    int o = idx >> 10;
    float4 c = reinterpret_cast<const float4*>(tc)[(size_t)o * IN_DIM + i];
    float  w = bw[(size_t)o * IN_DIM + i];
    union { __half h[4]; uint2 u; } H;
    H.h[0] = __float2half(c.y);
    H.h[1] = __float2half(c.z);
    H.h[2] = __float2half(c.w);
    H.h[3] = __float2half(w);
    reinterpret_cast<uint2*>(g_Bh)[(size_t)o * IN_DIM + i] = H.u;
}

// ---------------------------------------------------------------------------
// bias'[o] = bias[o] + sum_i C[o,i,0]
// ---------------------------------------------------------------------------
__global__ void bias_kernel(const float* __restrict__ tc,
                            const float* __restrict__ bias) {
    int o = blockIdx.x;
    float s = 0.f;
    for (int i = threadIdx.x; i < IN_DIM; i += 256)
        s += tc[(size_t)o * (IN_DIM * 4) + (size_t)i * 4];
    #pragma unroll
    for (int off = 16; off; off >>= 1)
        s += __shfl_down_sync(0xffffffffu, s, off);
    __shared__ float red[8];
    if ((threadIdx.x & 31) == 0) red[threadIdx.x >> 5] = s;
    __syncthreads();
    if (threadIdx.x < 8) {
        s = red[threadIdx.x];
        #pragma unroll
        for (int off = 4; off; off >>= 1)
            s += __shfl_down_sync(0xffu, s, off);
        if (threadIdx.x == 0) g_biasp[o] = s + bias[o];
    }
}

// ---------------------------------------------------------------------------
// Load one pipeline stage: Ah [128x32] + Bh [128x32] fp16, padded 80B rows.
// 4 x cp.async(16B) per thread.
// ---------------------------------------------------------------------------
__device__ __forceinline__ void load_stage(uint32_t stg, int k0, int bm, int bn,
                                           int tid) {
    #pragma unroll
    for (int r = 0; r < 2; r++) {
        int s   = tid + r * THREADS;       // 0..511
        int row = s >> 2;                  // 0..127
        int c   = s & 3;                   // 16B seg within 64B row
        uint32_t so = (uint32_t)(row * ROWB + c * 16);
        size_t ga = (size_t)(bm + row) * KV + k0 + c * 8;
        size_t gb = (size_t)(bn + row) * KV + k0 + c * 8;
        cpa16(stg + 0 * TILEB + so, g_Fh + ga);
        cpa16(stg + 1 * TILEB + so, g_Bh + gb);
    }
}

// ---------------------------------------------------------------------------
// GEMM via mma.sync fp16, single pass: out = Ah@Bh^T + bias
// 8 warps, warp tile 64x32 (4x4 grid of m16n8k16). 2 CTAs/SM, 4-stage pipe.
// ---------------------------------------------------------------------------
__global__ void __launch_bounds__(THREADS, 2) gemm_kernel(float* __restrict__ out) {
    extern __shared__ __align__(128) char smem_raw[];
    const int tid    = threadIdx.x;
    const int wid    = tid >> 5;
    const int lane   = tid & 31;
    const int warp_m = wid >> 2;           // 0..1  -> 64 rows
    const int warp_n = wid & 3;            // 0..3  -> 32 cols
    const int bm     = blockIdx.y * BM;
    const int bn     = blockIdx.x * BN;

    const uint32_t sb = (uint32_t)__cvta_generic_to_shared(smem_raw);

    // per-thread invariant ldmatrix offsets
    const uint32_t a_off = (uint32_t)((warp_m * 64 + (lane & 15)) * ROWB +
                                      (lane >> 4) * 16);
    const int bquad = lane >> 3;           // 0..3
    const uint32_t b_off = (uint32_t)((warp_n * 32 + ((bquad >> 1) * 8) +
                                       (lane & 7)) * ROWB + (bquad & 1) * 16);

    float acc[4][4][4];
    #pragma unroll
    for (int mi = 0; mi < 4; mi++)
        #pragma unroll
        for (int ni = 0; ni < 4; ni++)
            #pragma unroll
            for (int q = 0; q < 4; q++) acc[mi][ni][q] = 0.f;

    // Prologue: stages 0..2
    load_stage(sb + 0 * STAGE_BYTES, 0 * KC, bm, bn, tid);
    CP_COMMIT();
    load_stage(sb + 1 * STAGE_BYTES, 1 * KC, bm, bn, tid);
    CP_COMMIT();
    load_stage(sb + 2 * STAGE_BYTES, 2 * KC, bm, bn, tid);
    CP_COMMIT();

    #pragma unroll 1
    for (int i = 0; i < NCHUNK; i++) {
        if      (i <= NCHUNK - 3) asm volatile("cp.async.wait_group 2;" ::: "memory");
        else if (i == NCHUNK - 2) asm volatile("cp.async.wait_group 1;" ::: "memory");
        else                      asm volatile("cp.async.wait_group 0;" ::: "memory");
        __syncthreads();

        const uint32_t stg = sb + (uint32_t)(i % STAGES) * STAGE_BYTES;

        if (i + 3 < NCHUNK) {
            load_stage(sb + (uint32_t)((i + 3) % STAGES) * STAGE_BYTES,
                       (i + 3) * KC, bm, bn, tid);
            CP_COMMIT();
        }

        #pragma unroll
        for (int ks = 0; ks < 2; ks++) {
            uint32_t ah[4][4], bh[2][4];
            const uint32_t kso = (uint32_t)(ks * 32);
            #pragma unroll
            for (int mi = 0; mi < 4; mi++) {
                uint32_t ao = a_off + (uint32_t)(mi * 16 * ROWB) + kso;
                ldm4(ah[mi], stg + 0 * TILEB + ao);
            }
            #pragma unroll
            for (int p = 0; p < 2; p++) {
                uint32_t bo = b_off + (uint32_t)(p * 16 * ROWB) + kso;
                ldm4(bh[p], stg + 1 * TILEB + bo);
            }
            #pragma unroll
            for (int mi = 0; mi < 4; mi++)
                #pragma unroll
                for (int ni = 0; ni < 4; ni++)
                    mma16816(acc[mi][ni], ah[mi], &bh[ni >> 1][(ni & 1) * 2]);
        }
    }

    // Epilogue: bias + store (float2 per fragment pair)
    #pragma unroll
    for (int mi = 0; mi < 4; mi++) {
        const int r0 = bm + warp_m * 64 + mi * 16 + (lane >> 2);
        #pragma unroll
        for (int ni = 0; ni < 4; ni++) {
            const int c = bn + warp_n * 32 + ni * 8 + (lane & 3) * 2;
            const float b0 = g_biasp[c];
            const float b1 = g_biasp[c + 1];
            float2 v0 = make_float2(acc[mi][ni][0] + b0, acc[mi][ni][1] + b1);
            float2 v1 = make_float2(acc[mi][ni][2] + b0, acc[mi][ni][3] + b1);
            *reinterpret_cast<float2*>(out + (size_t)r0 * N_DIM + c)       = v0;
            *reinterpret_cast<float2*>(out + (size_t)(r0 + 8) * N_DIM + c) = v1;
        }
    }
}

// ---------------------------------------------------------------------------
extern "C" void kernel_launch(void* const* d_in, const int* in_sizes, int n_in,
                              void* d_out, int out_size) {
    const float* x = nullptr;
    const float* bw = nullptr;
    const float* tc = nullptr;
    const float* bias = nullptr;
    for (int i = 0; i < n_in; i++) {
        long sz = in_sizes[i];
        if      (sz == 8388608L) x    = (const float*)d_in[i];
        else if (sz == 1048576L) bw   = (const float*)d_in[i];
        else if (sz == 4194304L) tc   = (const float*)d_in[i];
        else if (sz == 1024L)    bias = (const float*)d_in[i];
    }
    float* out = (float*)d_out;

    cudaFuncSetAttribute(gemm_kernel,
                         cudaFuncAttributeMaxDynamicSharedMemorySize, SMEM_ALLOC);

    feat_kernel<<<(M_DIM * IN_DIM) / 256, 256>>>(x);
    pack_kernel<<<(N_DIM * IN_DIM) / 256, 256>>>(tc, bw);
    bias_kernel<<<N_DIM, 256>>>(tc, bias);

    dim3 grid(N_DIM / BN, M_DIM / BM);   // (8, 64) = 512 CTAs
    gemm_kernel<<<grid, THREADS, SMEM_ALLOC>>>(out);
}